// round 6
// baseline (speedup 1.0000x reference)
#include <cuda_runtime.h>
#include <cuda_fp16.h>
#include <cuda_bf16.h>
#include <math.h>
#include <stdint.h>

#define N_SRC 100000
#define N_DST 50000
#define D_IN  128
#define D_OUT 64
#define BUCKET 128

#define TILES_Y 1563           // ceil(100000/64)
#define TILES_Z 782            // ceil(50000/64)

// ---------------- scratch (device globals; no allocations allowed) ---------
__device__ __half g_yh[(size_t)N_SRC * D_OUT];     // fp16(x @ W_l)   12.8 MB
__device__ float  g_z[(size_t)N_DST * D_OUT];      // x[:N_DST]@W_r   12.8 MB
__device__ int    g_cnt[N_DST];
__device__ int    g_src[(size_t)N_DST * BUCKET];   // bucketed CSR    25.6 MB
// W^T split into bf16 hi/lo, [n][k] row-major
__device__ __nv_bfloat16 g_wt1l[64 * 128], g_wt2l[64 * 128];
__device__ __nv_bfloat16 g_wt1r[64 * 128], g_wt2r[64 * 128];

__device__ __forceinline__ uint32_t smem_u32(const void* p) {
    uint32_t a;
    asm("{ .reg .u64 t; cvta.to.shared.u64 t, %1; cvt.u32.u64 %0, t; }"
        : "=r"(a) : "l"(p));
    return a;
}

// ---------------------------------------------------------------------------
__global__ void zero_cnt_kernel() {
    int i = blockIdx.x * blockDim.x + threadIdx.x;
    if (i < N_DST) g_cnt[i] = 0;
}

// ---------------------------------------------------------------------------
// W^T bf16 hi/lo split: wt[n][k] = W[k][n]
__global__ void wt_prep_kernel(const float* __restrict__ Wl,
                               const float* __restrict__ Wr) {
    int i = blockIdx.x * blockDim.x + threadIdx.x;
    if (i >= 64 * 128) return;
    int n = i & 63, k = i >> 6;
    float vl = Wl[k * 64 + n];
    __nv_bfloat16 h = __float2bfloat16(vl);
    g_wt1l[n * 128 + k] = h;
    g_wt2l[n * 128 + k] = __float2bfloat16(vl - __bfloat162float(h));
    float vr = Wr[k * 64 + n];
    __nv_bfloat16 g = __float2bfloat16(vr);
    g_wt1r[n * 128 + k] = g;
    g_wt2r[n * 128 + k] = __float2bfloat16(vr - __bfloat162float(g));
}

// ---------------------------------------------------------------------------
__global__ void fill_kernel(const void* __restrict__ eiv, int n_edges) {
    const unsigned long long* q = (const unsigned long long*)eiv;
    bool is64 = (((q[0] | q[1] | q[2] | q[3]) >> 32) == 0ULL);

    int stride = gridDim.x * blockDim.x;
    for (int e = blockIdx.x * blockDim.x + threadIdx.x; e < n_edges; e += stride) {
        int s, d;
        if (is64) {
            const long long* ei = (const long long*)eiv;
            s = (int)ei[e];
            d = (int)ei[n_edges + e];
        } else {
            const int* ei = (const int*)eiv;
            s = ei[e];
            d = ei[n_edges + e];
        }
        int slot = atomicAdd(&g_cnt[d], 1);
        if (slot < BUCKET)
            g_src[(size_t)d * BUCKET + slot] = s;
    }
}

// ---------------------------------------------------------------------------
// HMMA GEMM: one 64x64 tile per CTA, 4 warps (16 rows each), 3 CTAs/SM.
// D = A1@W1 + A1@W2 + A2@W1 (2-term bf16 split, fp32 accumulate).
#define ASTR 136
__global__ __launch_bounds__(128, 3) void gemm_mma_kernel(const float* __restrict__ x) {
    extern __shared__ __align__(16) char smem_raw[];
    __nv_bfloat16* A1 = (__nv_bfloat16*)smem_raw;            // 64 x 136
    __nv_bfloat16* A2 = A1 + 64 * ASTR;
    __nv_bfloat16* B1 = A2 + 64 * ASTR;                      // 64 x 136
    __nv_bfloat16* B2 = B1 + 64 * ASTR;

    int tid = threadIdx.x, warp = tid >> 5, lane = tid & 31;

    int b = blockIdx.x;
    bool is_y;
    int row0, M;
    const __nv_bfloat16 *wt1, *wt2;
    if (b < TILES_Y) { row0 = b << 6;             M = N_SRC; wt1 = g_wt1l; wt2 = g_wt2l; is_y = true;  }
    else             { row0 = (b - TILES_Y) << 6; M = N_DST; wt1 = g_wt1r; wt2 = g_wt2r; is_y = false; }

    // Load x tile (64x128 fp32), split to bf16 hi/lo
    #pragma unroll
    for (int i = tid; i < 64 * 32; i += 128) {
        int row = i >> 5, c4 = (i & 31) << 2;
        float4 v = make_float4(0.f, 0.f, 0.f, 0.f);
        if (row0 + row < M)
            v = *(const float4*)(x + (size_t)(row0 + row) * D_IN + c4);
        __nv_bfloat16 h0 = __float2bfloat16(v.x), h1 = __float2bfloat16(v.y);
        __nv_bfloat16 h2 = __float2bfloat16(v.z), h3 = __float2bfloat16(v.w);
        __nv_bfloat16 r0 = __float2bfloat16(v.x - __bfloat162float(h0));
        __nv_bfloat16 r1 = __float2bfloat16(v.y - __bfloat162float(h1));
        __nv_bfloat16 r2 = __float2bfloat16(v.z - __bfloat162float(h2));
        __nv_bfloat16 r3 = __float2bfloat16(v.w - __bfloat162float(h3));
        int idx = row * ASTR + c4;
        uint2 hi, lo;
        hi.x = (uint32_t)__bfloat16_as_ushort(h0) | ((uint32_t)__bfloat16_as_ushort(h1) << 16);
        hi.y = (uint32_t)__bfloat16_as_ushort(h2) | ((uint32_t)__bfloat16_as_ushort(h3) << 16);
        lo.x = (uint32_t)__bfloat16_as_ushort(r0) | ((uint32_t)__bfloat16_as_ushort(r1) << 16);
        lo.y = (uint32_t)__bfloat16_as_ushort(r2) | ((uint32_t)__bfloat16_as_ushort(r3) << 16);
        *(uint2*)(A1 + idx) = hi;
        *(uint2*)(A2 + idx) = lo;
    }
    // Load W^T hi/lo (64 rows x 128 k)
    #pragma unroll
    for (int i = tid; i < 64 * 16; i += 128) {
        int n = i >> 4, k8 = (i & 15) << 3;
        int idx = n * ASTR + k8;
        *(uint4*)(B1 + idx) = *(const uint4*)(wt1 + n * 128 + k8);
        *(uint4*)(B2 + idx) = *(const uint4*)(wt2 + n * 128 + k8);
    }
    __syncthreads();

    int m0 = warp << 4;
    float c[8][4];
    #pragma unroll
    for (int n = 0; n < 8; n++)
        #pragma unroll
        for (int j = 0; j < 4; j++) c[n][j] = 0.f;

    uint32_t a1b = smem_u32(A1), a2b = smem_u32(A2);
    uint32_t b1b = smem_u32(B1), b2b = smem_u32(B2);
    // A-ldmatrix lane offset (16 rows x2 8-col halves); B-x4 lane offset
    uint32_t aoff = (((m0 + (lane & 15)) * ASTR + ((lane >> 4) << 3)) << 1);
    uint32_t boff = (((((lane >> 4) << 3) + (lane & 7)) * ASTR + (((lane >> 3) & 1) << 3)) << 1);

    #pragma unroll 1
    for (int pass = 0; pass < 3; pass++) {
        uint32_t abase = ((pass == 2) ? a2b : a1b) + aoff;
        uint32_t bbase = ((pass == 1) ? b2b : b1b) + boff;
        #pragma unroll
        for (int k = 0; k < 8; k++) {
            uint32_t a0, a1, a2, a3;
            asm volatile("ldmatrix.sync.aligned.m8n8.x4.shared.b16 {%0,%1,%2,%3}, [%4];"
                         : "=r"(a0), "=r"(a1), "=r"(a2), "=r"(a3)
                         : "r"(abase + (k << 5)));
            #pragma unroll
            for (int p = 0; p < 4; p++) {
                uint32_t b0, b1, b2, b3;
                asm volatile("ldmatrix.sync.aligned.m8n8.x4.shared.b16 {%0,%1,%2,%3}, [%4];"
                             : "=r"(b0), "=r"(b1), "=r"(b2), "=r"(b3)
                             : "r"(bbase + ((p * ASTR) << 5) + (k << 5)));
                int n = p << 1;
                asm volatile(
                    "mma.sync.aligned.m16n8k16.row.col.f32.bf16.bf16.f32 "
                    "{%0,%1,%2,%3}, {%4,%5,%6,%7}, {%8,%9}, {%0,%1,%2,%3};"
                    : "+f"(c[n][0]), "+f"(c[n][1]), "+f"(c[n][2]), "+f"(c[n][3])
                    : "r"(a0), "r"(a1), "r"(a2), "r"(a3), "r"(b0), "r"(b1));
                asm volatile(
                    "mma.sync.aligned.m16n8k16.row.col.f32.bf16.bf16.f32 "
                    "{%0,%1,%2,%3}, {%4,%5,%6,%7}, {%8,%9}, {%0,%1,%2,%3};"
                    : "+f"(c[n+1][0]), "+f"(c[n+1][1]), "+f"(c[n+1][2]), "+f"(c[n+1][3])
                    : "r"(a0), "r"(a1), "r"(a2), "r"(a3), "r"(b2), "r"(b3));
            }
        }
    }

    // Epilogue: c fragment (row gr=lane/4 [+8], cols n*8 + 2*(lane%4) +{0,1})
    int gr = lane >> 2, gc = (lane & 3) << 1;
    int r0 = row0 + m0 + gr;
    int r1 = r0 + 8;
    if (is_y) {
        #pragma unroll
        for (int n = 0; n < 8; n++) {
            int col = (n << 3) + gc;
            if (r0 < M)
                *(__half2*)(g_yh + (size_t)r0 * D_OUT + col) =
                    __floats2half2_rn(c[n][0], c[n][1]);
            if (r1 < M)
                *(__half2*)(g_yh + (size_t)r1 * D_OUT + col) =
                    __floats2half2_rn(c[n][2], c[n][3]);
        }
    } else {
        #pragma unroll
        for (int n = 0; n < 8; n++) {
            int col = (n << 3) + gc;
            if (r0 < M)
                *(float2*)(g_z + (size_t)r0 * D_OUT + col) = make_float2(c[n][0], c[n][1]);
            if (r1 < M)
                *(float2*)(g_z + (size_t)r1 * D_OUT + col) = make_float2(c[n][2], c[n][3]);
        }
    }
}
#define SM_TOTAL (4 * 64 * ASTR * 2)

// ---------------------------------------------------------------------------
// Gather + finalize: one warp per dst row, 4 edges in flight per warp.
// lane = sub*8 + l : sub in [0,4) picks edge of the quad, l in [0,8) owns
// cols 8l..8l+7 (one uint4 = 8 halves). Indices prefetched one chunk ahead.
__global__ __launch_bounds__(256) void gather_finalize_kernel(
        float* __restrict__ out, const float* __restrict__ b_l) {
    int warp = (blockIdx.x * blockDim.x + threadIdx.x) >> 5;
    int lane = threadIdx.x & 31;
    if (warp >= N_DST) return;

    int cnt = g_cnt[warp];
    int n = cnt < BUCKET ? cnt : BUCKET;
    const int* bucket = g_src + (size_t)warp * BUCKET;
    int sub = lane >> 3;
    int l   = lane & 7;
    const uint4* yh4 = (const uint4*)g_yh;    // row r -> yh4[r*8 + l]

    float a0 = 0.f, a1 = 0.f, a2 = 0.f, a3 = 0.f;
    float a4 = 0.f, a5 = 0.f, a6 = 0.f, a7 = 0.f;
    if (n > 0) {
        int4 nxt = *(const int4*)bucket;
        for (int g = 0; g < n; g += 4) {
            int4 cur = nxt;
            if (g + 4 < n) nxt = *(const int4*)(bucket + g + 4);
            int s = (sub == 0) ? cur.x : (sub == 1) ? cur.y
                  : (sub == 2) ? cur.z : cur.w;
            uint4 u = make_uint4(0u, 0u, 0u, 0u);
            if (g + sub < n) u = yh4[((size_t)s << 3) + l];
            float2 p0 = __half22float2(*(__half2*)&u.x);
            float2 p1 = __half22float2(*(__half2*)&u.y);
            float2 p2 = __half22float2(*(__half2*)&u.z);
            float2 p3 = __half22float2(*(__half2*)&u.w);
            a0 += p0.x; a1 += p0.y; a2 += p1.x; a3 += p1.y;
            a4 += p2.x; a5 += p2.y; a6 += p3.x; a7 += p3.y;
        }
    }
    // merge the four sub-groups (lanes with equal l)
    #pragma unroll
    for (int o = 8; o <= 16; o <<= 1) {
        a0 += __shfl_xor_sync(0xffffffffu, a0, o);
        a1 += __shfl_xor_sync(0xffffffffu, a1, o);
        a2 += __shfl_xor_sync(0xffffffffu, a2, o);
        a3 += __shfl_xor_sync(0xffffffffu, a3, o);
        a4 += __shfl_xor_sync(0xffffffffu, a4, o);
        a5 += __shfl_xor_sync(0xffffffffu, a5, o);
        a6 += __shfl_xor_sync(0xffffffffu, a6, o);
        a7 += __shfl_xor_sync(0xffffffffu, a7, o);
    }

    float inv = 1.0f / fmaxf((float)cnt, 1.0f);
    const float* zp = g_z + (size_t)warp * D_OUT + (l << 3);
    float4 z0 = *(const float4*)zp;
    float4 z1 = *(const float4*)(zp + 4);
    float4 b0 = *(const float4*)(b_l + (l << 3));
    float4 b1 = *(const float4*)(b_l + (l << 3) + 4);

    float v0 = a0 * inv + b0.x + z0.x;
    float v1 = a1 * inv + b0.y + z0.y;
    float v2 = a2 * inv + b0.z + z0.z;
    float v3 = a3 * inv + b0.w + z0.w;
    float v4 = a4 * inv + b1.x + z1.x;
    float v5 = a5 * inv + b1.y + z1.y;
    float v6 = a6 * inv + b1.z + z1.z;
    float v7 = a7 * inv + b1.w + z1.w;

    float m = fmaxf(fmaxf(fmaxf(v0, v1), fmaxf(v2, v3)),
                    fmaxf(fmaxf(v4, v5), fmaxf(v6, v7)));
    #pragma unroll
    for (int o = 4; o; o >>= 1) m = fmaxf(m, __shfl_xor_sync(0xffffffffu, m, o));

    float s = expf(v0 - m) + expf(v1 - m) + expf(v2 - m) + expf(v3 - m)
            + expf(v4 - m) + expf(v5 - m) + expf(v6 - m) + expf(v7 - m);
    #pragma unroll
    for (int o = 4; o; o >>= 1) s += __shfl_xor_sync(0xffffffffu, s, o);

    float lz = m + logf(s);
    if (sub == 0) {
        float* op = out + (size_t)warp * D_OUT + (l << 3);
        *(float4*)op       = make_float4(v0 - lz, v1 - lz, v2 - lz, v3 - lz);
        *(float4*)(op + 4) = make_float4(v4 - lz, v5 - lz, v6 - lz, v7 - lz);
    }
}

// ---------------------------------------------------------------------------
extern "C" void kernel_launch(void* const* d_in, const int* in_sizes, int n_in,
                              void* d_out, int out_size) {
    const float* x  = (const float*)d_in[0];
    const float* Wl = (const float*)d_in[1];
    const float* bl = (const float*)d_in[2];
    const float* Wr = (const float*)d_in[3];
    const void*  ei = d_in[4];
    int n_edges = in_sizes[4] / 2;
    float* out = (float*)d_out;

    zero_cnt_kernel<<<(N_DST + 255) / 256, 256>>>();
    wt_prep_kernel<<<32, 256>>>(Wl, Wr);
    fill_kernel<<<2048, 256>>>(ei, n_edges);

    cudaFuncSetAttribute(gemm_mma_kernel,
                         cudaFuncAttributeMaxDynamicSharedMemorySize, SM_TOTAL);
    gemm_mma_kernel<<<TILES_Y + TILES_Z, 128, SM_TOTAL>>>(x);

    gather_finalize_kernel<<<(N_DST * 32 + 255) / 256, 256>>>(out, bl);
}

// round 7
// speedup vs baseline: 1.1668x; 1.1668x over previous
#include <cuda_runtime.h>
#include <cuda_fp16.h>
#include <cuda_bf16.h>
#include <math.h>
#include <stdint.h>

#define N_SRC 100000
#define N_DST 50000
#define D_IN  128
#define D_OUT 64
#define BUCKET 128

#define TILES_Y 1563           // ceil(100000/64)
#define TILES_Z 782            // ceil(50000/64)

// ---------------- scratch (device globals; no allocations allowed) ---------
__device__ __half g_yh[(size_t)N_SRC * D_OUT];     // fp16(x @ W_l)   12.8 MB
__device__ float  g_z[(size_t)N_DST * D_OUT];      // x[:N_DST]@W_r   12.8 MB
__device__ int    g_cnt[N_DST];
__device__ int    g_src[(size_t)N_DST * BUCKET];   // bucketed CSR    25.6 MB
// W^T split into bf16 hi/lo, [n][k] row-major
__device__ __nv_bfloat16 g_wt1l[64 * 128], g_wt2l[64 * 128];
__device__ __nv_bfloat16 g_wt1r[64 * 128], g_wt2r[64 * 128];

__device__ __forceinline__ uint32_t smem_u32(const void* p) {
    uint32_t a;
    asm("{ .reg .u64 t; cvta.to.shared.u64 t, %1; cvt.u32.u64 %0, t; }"
        : "=r"(a) : "l"(p));
    return a;
}

// ---------------------------------------------------------------------------
// zero counters + W^T bf16 hi/lo split (wt[n][k] = W[k][n]) in one launch
__global__ void prep_kernel(const float* __restrict__ Wl,
                            const float* __restrict__ Wr) {
    int i = blockIdx.x * blockDim.x + threadIdx.x;
    if (i < N_DST) g_cnt[i] = 0;
    if (i < 64 * 128) {
        int n = i & 63, k = i >> 6;
        float vl = Wl[k * 64 + n];
        __nv_bfloat16 h = __float2bfloat16(vl);
        g_wt1l[n * 128 + k] = h;
        g_wt2l[n * 128 + k] = __float2bfloat16(vl - __bfloat162float(h));
        float vr = Wr[k * 64 + n];
        __nv_bfloat16 g = __float2bfloat16(vr);
        g_wt1r[n * 128 + k] = g;
        g_wt2r[n * 128 + k] = __float2bfloat16(vr - __bfloat162float(g));
    }
}

// ---------------------------------------------------------------------------
__global__ void fill_kernel(const void* __restrict__ eiv, int n_edges) {
    const unsigned long long* q = (const unsigned long long*)eiv;
    bool is64 = (((q[0] | q[1] | q[2] | q[3]) >> 32) == 0ULL);

    int stride = gridDim.x * blockDim.x;
    for (int e = blockIdx.x * blockDim.x + threadIdx.x; e < n_edges; e += stride) {
        int s, d;
        if (is64) {
            const long long* ei = (const long long*)eiv;
            s = (int)ei[e];
            d = (int)ei[n_edges + e];
        } else {
            const int* ei = (const int*)eiv;
            s = ei[e];
            d = ei[n_edges + e];
        }
        int slot = atomicAdd(&g_cnt[d], 1);
        if (slot < BUCKET)
            g_src[(size_t)d * BUCKET + slot] = s;
    }
}

// ---------------------------------------------------------------------------
// HMMA GEMM: one 64x64 tile per CTA, 4 warps (16 rows each), 3 CTAs/SM.
// D = A1@W1 + A1@W2 + A2@W1 (2-term bf16 split, fp32 accumulate).
// Passes FUSED into one k-loop: A/B fragments loaded once per k, all three
// products accumulate into the same c — 33% less ldmatrix traffic.
#define ASTR 136
__global__ __launch_bounds__(128, 3) void gemm_mma_kernel(const float* __restrict__ x) {
    extern __shared__ __align__(16) char smem_raw[];
    __nv_bfloat16* A1 = (__nv_bfloat16*)smem_raw;            // 64 x 136
    __nv_bfloat16* A2 = A1 + 64 * ASTR;
    __nv_bfloat16* B1 = A2 + 64 * ASTR;                      // 64 x 136
    __nv_bfloat16* B2 = B1 + 64 * ASTR;

    int tid = threadIdx.x, warp = tid >> 5, lane = tid & 31;

    int b = blockIdx.x;
    bool is_y;
    int row0, M;
    const __nv_bfloat16 *wt1, *wt2;
    if (b < TILES_Y) { row0 = b << 6;             M = N_SRC; wt1 = g_wt1l; wt2 = g_wt2l; is_y = true;  }
    else             { row0 = (b - TILES_Y) << 6; M = N_DST; wt1 = g_wt1r; wt2 = g_wt2r; is_y = false; }

    // Load x tile (64x128 fp32), split to bf16 hi/lo
    #pragma unroll
    for (int i = tid; i < 64 * 32; i += 128) {
        int row = i >> 5, c4 = (i & 31) << 2;
        float4 v = make_float4(0.f, 0.f, 0.f, 0.f);
        if (row0 + row < M)
            v = *(const float4*)(x + (size_t)(row0 + row) * D_IN + c4);
        __nv_bfloat16 h0 = __float2bfloat16(v.x), h1 = __float2bfloat16(v.y);
        __nv_bfloat16 h2 = __float2bfloat16(v.z), h3 = __float2bfloat16(v.w);
        __nv_bfloat16 r0 = __float2bfloat16(v.x - __bfloat162float(h0));
        __nv_bfloat16 r1 = __float2bfloat16(v.y - __bfloat162float(h1));
        __nv_bfloat16 r2 = __float2bfloat16(v.z - __bfloat162float(h2));
        __nv_bfloat16 r3 = __float2bfloat16(v.w - __bfloat162float(h3));
        int idx = row * ASTR + c4;
        uint2 hi, lo;
        hi.x = (uint32_t)__bfloat16_as_ushort(h0) | ((uint32_t)__bfloat16_as_ushort(h1) << 16);
        hi.y = (uint32_t)__bfloat16_as_ushort(h2) | ((uint32_t)__bfloat16_as_ushort(h3) << 16);
        lo.x = (uint32_t)__bfloat16_as_ushort(r0) | ((uint32_t)__bfloat16_as_ushort(r1) << 16);
        lo.y = (uint32_t)__bfloat16_as_ushort(r2) | ((uint32_t)__bfloat16_as_ushort(r3) << 16);
        *(uint2*)(A1 + idx) = hi;
        *(uint2*)(A2 + idx) = lo;
    }
    // Load W^T hi/lo (64 rows x 128 k)
    #pragma unroll
    for (int i = tid; i < 64 * 16; i += 128) {
        int n = i >> 4, k8 = (i & 15) << 3;
        int idx = n * ASTR + k8;
        *(uint4*)(B1 + idx) = *(const uint4*)(wt1 + n * 128 + k8);
        *(uint4*)(B2 + idx) = *(const uint4*)(wt2 + n * 128 + k8);
    }
    __syncthreads();

    int m0 = warp << 4;
    float c[8][4];
    #pragma unroll
    for (int n = 0; n < 8; n++)
        #pragma unroll
        for (int j = 0; j < 4; j++) c[n][j] = 0.f;

    uint32_t a1b = smem_u32(A1), a2b = smem_u32(A2);
    uint32_t b1b = smem_u32(B1), b2b = smem_u32(B2);
    uint32_t aoff = (((m0 + (lane & 15)) * ASTR + ((lane >> 4) << 3)) << 1);
    uint32_t boff = (((((lane >> 4) << 3) + (lane & 7)) * ASTR + (((lane >> 3) & 1) << 3)) << 1);

    #pragma unroll 2
    for (int k = 0; k < 8; k++) {
        uint32_t ka = (k << 5);
        uint32_t x0, x1, x2, x3, y0, y1, y2, y3;
        asm volatile("ldmatrix.sync.aligned.m8n8.x4.shared.b16 {%0,%1,%2,%3}, [%4];"
                     : "=r"(x0), "=r"(x1), "=r"(x2), "=r"(x3)
                     : "r"(a1b + aoff + ka));
        asm volatile("ldmatrix.sync.aligned.m8n8.x4.shared.b16 {%0,%1,%2,%3}, [%4];"
                     : "=r"(y0), "=r"(y1), "=r"(y2), "=r"(y3)
                     : "r"(a2b + aoff + ka));
        #pragma unroll
        for (int p = 0; p < 4; p++) {
            uint32_t po = ((p * ASTR) << 5) + ka;
            uint32_t u0, u1, u2, u3, w0, w1, w2, w3;
            asm volatile("ldmatrix.sync.aligned.m8n8.x4.shared.b16 {%0,%1,%2,%3}, [%4];"
                         : "=r"(u0), "=r"(u1), "=r"(u2), "=r"(u3)
                         : "r"(b1b + boff + po));
            asm volatile("ldmatrix.sync.aligned.m8n8.x4.shared.b16 {%0,%1,%2,%3}, [%4];"
                         : "=r"(w0), "=r"(w1), "=r"(w2), "=r"(w3)
                         : "r"(b2b + boff + po));
            int n = p << 1;
            #define MMA(CN, B0, B1v)                                            \
                asm volatile(                                                   \
                    "mma.sync.aligned.m16n8k16.row.col.f32.bf16.bf16.f32 "      \
                    "{%0,%1,%2,%3}, {%4,%5,%6,%7}, {%8,%9}, {%0,%1,%2,%3};"     \
                    : "+f"(c[CN][0]), "+f"(c[CN][1]), "+f"(c[CN][2]), "+f"(c[CN][3]) \
                    : "r"(A0_), "r"(A1_), "r"(A2_), "r"(A3_), "r"(B0), "r"(B1v))
            #define A0_ x0
            #define A1_ x1
            #define A2_ x2
            #define A3_ x3
            MMA(n, u0, u1);      // A1*B1
            MMA(n + 1, u2, u3);
            MMA(n, w0, w1);      // A1*B2
            MMA(n + 1, w2, w3);
            #undef A0_
            #undef A1_
            #undef A2_
            #undef A3_
            #define A0_ y0
            #define A1_ y1
            #define A2_ y2
            #define A3_ y3
            MMA(n, u0, u1);      // A2*B1
            MMA(n + 1, u2, u3);
            #undef A0_
            #undef A1_
            #undef A2_
            #undef A3_
            #undef MMA
        }
    }

    // Epilogue: c fragment (row gr=lane/4 [+8], cols n*8 + 2*(lane%4) +{0,1})
    int gr = lane >> 2, gc = (lane & 3) << 1;
    int r0 = row0 + m0 + gr;
    int r1 = r0 + 8;
    if (is_y) {
        #pragma unroll
        for (int n = 0; n < 8; n++) {
            int col = (n << 3) + gc;
            if (r0 < M)
                *(__half2*)(g_yh + (size_t)r0 * D_OUT + col) =
                    __floats2half2_rn(c[n][0], c[n][1]);
            if (r1 < M)
                *(__half2*)(g_yh + (size_t)r1 * D_OUT + col) =
                    __floats2half2_rn(c[n][2], c[n][3]);
        }
    } else {
        #pragma unroll
        for (int n = 0; n < 8; n++) {
            int col = (n << 3) + gc;
            if (r0 < M)
                *(float2*)(g_z + (size_t)r0 * D_OUT + col) = make_float2(c[n][0], c[n][1]);
            if (r1 < M)
                *(float2*)(g_z + (size_t)r1 * D_OUT + col) = make_float2(c[n][2], c[n][3]);
        }
    }
}
#define SM_TOTAL (4 * 64 * ASTR * 2)

// ---------------------------------------------------------------------------
// Gather + finalize: one warp per dst row; lane owns cols {2l, 2l+1} (half2).
// 8 independent edges in flight per lane per iteration (MLP=8) with int4
// index prefetch. Then mean + bias + self-term + log_softmax.
__global__ __launch_bounds__(256) void gather_finalize_kernel(
        float* __restrict__ out, const float* __restrict__ b_l) {
    int warp = (blockIdx.x * blockDim.x + threadIdx.x) >> 5;
    int lane = threadIdx.x & 31;
    if (warp >= N_DST) return;

    int cnt = g_cnt[warp];
    int n = cnt < BUCKET ? cnt : BUCKET;
    const int* bucket = g_src + (size_t)warp * BUCKET;
    const __half2* yh = (const __half2*)g_yh + lane;   // row r -> yh[r*32]

    float a0 = 0.f, a1 = 0.f;
    if (n > 0) {
        int4 p0 = *(const int4*)bucket;
        int4 p1 = *(const int4*)(bucket + 4);
        for (int g = 0; g < n; g += 8) {
            int4 c0 = p0, c1 = p1;
            if (g + 8 < n) {
                p0 = *(const int4*)(bucket + g + 8);
                p1 = *(const int4*)(bucket + g + 12);
            }
            __half2 zero = __half2half2(__ushort_as_half(0));
            __half2 h0 = (g + 0 < n) ? yh[(size_t)c0.x << 5] : zero;
            __half2 h1 = (g + 1 < n) ? yh[(size_t)c0.y << 5] : zero;
            __half2 h2 = (g + 2 < n) ? yh[(size_t)c0.z << 5] : zero;
            __half2 h3 = (g + 3 < n) ? yh[(size_t)c0.w << 5] : zero;
            __half2 h4 = (g + 4 < n) ? yh[(size_t)c1.x << 5] : zero;
            __half2 h5 = (g + 5 < n) ? yh[(size_t)c1.y << 5] : zero;
            __half2 h6 = (g + 6 < n) ? yh[(size_t)c1.z << 5] : zero;
            __half2 h7 = (g + 7 < n) ? yh[(size_t)c1.w << 5] : zero;
            float2 f0 = __half22float2(h0), f1 = __half22float2(h1);
            float2 f2 = __half22float2(h2), f3 = __half22float2(h3);
            float2 f4 = __half22float2(h4), f5 = __half22float2(h5);
            float2 f6 = __half22float2(h6), f7 = __half22float2(h7);
            a0 += (f0.x + f1.x) + (f2.x + f3.x) + (f4.x + f5.x) + (f6.x + f7.x);
            a1 += (f0.y + f1.y) + (f2.y + f3.y) + (f4.y + f5.y) + (f6.y + f7.y);
        }
    }

    float inv = 1.0f / fmaxf((float)cnt, 1.0f);
    float2 zz = *(const float2*)(g_z + (size_t)warp * D_OUT + (lane << 1));
    float2 bb = *(const float2*)(b_l + (lane << 1));
    float v0 = a0 * inv + bb.x + zz.x;
    float v1 = a1 * inv + bb.y + zz.y;

    float m = fmaxf(v0, v1);
    #pragma unroll
    for (int o = 16; o; o >>= 1) m = fmaxf(m, __shfl_xor_sync(0xffffffffu, m, o));

    float s = expf(v0 - m) + expf(v1 - m);
    #pragma unroll
    for (int o = 16; o; o >>= 1) s += __shfl_xor_sync(0xffffffffu, s, o);

    float lz = m + logf(s);
    *(float2*)(out + (size_t)warp * D_OUT + (lane << 1)) =
        make_float2(v0 - lz, v1 - lz);
}

// ---------------------------------------------------------------------------
extern "C" void kernel_launch(void* const* d_in, const int* in_sizes, int n_in,
                              void* d_out, int out_size) {
    const float* x  = (const float*)d_in[0];
    const float* Wl = (const float*)d_in[1];
    const float* bl = (const float*)d_in[2];
    const float* Wr = (const float*)d_in[3];
    const void*  ei = d_in[4];
    int n_edges = in_sizes[4] / 2;
    float* out = (float*)d_out;

    prep_kernel<<<(N_DST + 255) / 256, 256>>>(Wl, Wr);
    fill_kernel<<<2048, 256>>>(ei, n_edges);

    cudaFuncSetAttribute(gemm_mma_kernel,
                         cudaFuncAttributeMaxDynamicSharedMemorySize, SM_TOTAL);
    gemm_mma_kernel<<<TILES_Y + TILES_Z, 128, SM_TOTAL>>>(x);

    gather_finalize_kernel<<<(N_DST * 32 + 255) / 256, 256>>>(out, bl);
}